// round 7
// baseline (speedup 1.0000x reference)
#include <cuda_runtime.h>
#include <cuda_bf16.h>

#define SEQ   4096
#define BATCH 256
#define DIN   64
#define DH    128

// 512 MB scratch for precomputed input projections x_proj[s][b][j].
__device__ float g_xproj[SEQ * BATCH * DH];

// ---------------------------------------------------------------------------
// Packed fp32x2 helpers (Blackwell: 2 FMAs per instruction).
// ---------------------------------------------------------------------------
__device__ __forceinline__ unsigned long long pack2(float lo, float hi) {
    unsigned long long r;
    asm("mov.b64 %0, {%1, %2};" : "=l"(r) : "f"(lo), "f"(hi));
    return r;
}

__device__ __forceinline__ float2 unpack2(unsigned long long v) {
    float2 f;
    asm("mov.b64 {%0, %1}, %2;" : "=f"(f.x), "=f"(f.y) : "l"(v));
    return f;
}

__device__ __forceinline__ void ffma2(unsigned long long& d,
                                      unsigned long long a,
                                      unsigned long long b) {
    asm("fma.rn.f32x2 %0, %1, %2, %0;" : "+l"(d) : "l"(a), "l"(b));
}

__device__ __forceinline__ unsigned long long fadd2(unsigned long long a,
                                                    unsigned long long b) {
    unsigned long long d;
    asm("add.rn.f32x2 %0, %1, %2;" : "=l"(d) : "l"(a), "l"(b));
    return d;
}

// tanh via 2x MUFU (EX2 + RCP), rel err ~2^-20.
__device__ __forceinline__ float fast_tanh(float x) {
    float e = __expf(x + x);
    return 1.0f - __fdividef(2.0f, e + 1.0f);
}

// ---------------------------------------------------------------------------
// Phase 1: x_proj[s,b,j] = dot(input[s,b,:], W_ih[j,:]) + b_ih[j] + b_hh[j]
// ---------------------------------------------------------------------------
__global__ void __launch_bounds__(128) xproj_kernel(
    const float* __restrict__ in,     // [SEQ*BATCH, DIN]
    const float* __restrict__ Wih,    // [DH, DIN]
    const float* __restrict__ bA,
    const float* __restrict__ bB)
{
    __shared__ __align__(16) float sin_t[16][DIN];   // 4 KB tile

    const int j = threadIdx.x;

    unsigned long long wp[32];
#pragma unroll
    for (int q = 0; q < 16; q++) {
        float4 v = *(const float4*)(Wih + j * DIN + q * 4);
        wp[2 * q]     = pack2(v.x, v.y);
        wp[2 * q + 1] = pack2(v.z, v.w);
    }
    const float bias = bA[j] + bB[j];

    const int ntiles = (SEQ * BATCH) / 16;
    for (int tile = blockIdx.x; tile < ntiles; tile += gridDim.x) {
        __syncthreads();   // WAR on sin_t reuse
        const float4* src = (const float4*)(in + tile * (16 * DIN));
        ((float4*)&sin_t[0][0])[j]       = src[j];
        ((float4*)&sin_t[0][0])[128 + j] = src[128 + j];
        __syncthreads();

        for (int r = 0; r < 16; r++) {
            unsigned long long acc[4] = {0ULL, 0ULL, 0ULL, 0ULL};
#pragma unroll
            for (int q = 0; q < 16; q++) {
                ulonglong2 hv = *(const ulonglong2*)&sin_t[r][q * 4];
                ffma2(acc[(q & 1) * 2],     wp[2 * q],     hv.x);
                ffma2(acc[(q & 1) * 2 + 1], wp[2 * q + 1], hv.y);
            }
            unsigned long long t = fadd2(fadd2(acc[0], acc[1]),
                                         fadd2(acc[2], acc[3]));
            float2 f = unpack2(t);
            __stcs(&g_xproj[(tile * 16 + r) * DH + j], f.x + f.y + bias);
        }
    }
}

// ---------------------------------------------------------------------------
// Phase 2: sequential scan. 256 blocks x 256 threads, one batch row per block.
// Thread (j = tid>>1, half = tid&1) holds HALF of W_hh row j (64 floats =
// 64 regs) and accumulates over its 64-element k-range; the lane pair
// (lanes 2i, 2i+1 of the same warp) combines partials with one shfl.xor(1).
// Register footprint ~105/thread -> 2 CTAs/SM (16 warps, 4 pipelines/SMSP),
// doubling latency hiding vs the previous 1-CTA layout and leaving ptxas
// headroom to pipeline the h-loads.
// ---------------------------------------------------------------------------
__global__ void __launch_bounds__(256, 2) rnn_scan_kernel(
    const float* __restrict__ Whh,    // [DH, DH]
    float* __restrict__ out)          // [BATCH, DH]
{
    const int tid  = threadIdx.x;
    const int j    = tid >> 1;        // output unit 0..127
    const int half = tid & 1;         // which 64-wide k-slice of row j
    const int row  = blockIdx.x;

    __shared__ __align__(16) float hbuf[2][DH];

    // Half of W_hh row j: 32 packed f32x2 pairs (64 registers).
    unsigned long long wp[32];
    {
        const float* wrow = Whh + j * DH + half * 64;
#pragma unroll
        for (int q = 0; q < 16; q++) {
            float4 v = *(const float4*)(wrow + q * 4);
            wp[2 * q]     = pack2(v.x, v.y);
            wp[2 * q + 1] = pack2(v.z, v.w);
        }
    }

    if (tid < DH) {                   // h0 = 0
        hbuf[0][tid] = 0.0f;
    }

    // Distance-2 x prefetch (streaming: 512 MB single-use).
    float xc = __ldcs(&g_xproj[(0 * BATCH + row) * DH + j]);
    float xn = __ldcs(&g_xproj[(1 * BATCH + row) * DH + j]);

    __syncthreads();

    int   cur = 0;
    float hn  = 0.0f;
    for (int s = 0; s < SEQ; s++) {
        const int sp = (s + 2 < SEQ) ? (s + 2) : (SEQ - 1);
        float xf = __ldcs(&g_xproj[(sp * BATCH + row) * DH + j]);

        const float* hh = hbuf[cur] + half * 64;
        // 8 accumulator chains, depth 4 each (short RAW chains).
        unsigned long long acc[8] = {0ULL,0ULL,0ULL,0ULL,0ULL,0ULL,0ULL,0ULL};
#pragma unroll
        for (int q = 0; q < 16; q++) {          // 4 floats of h per iter
            ulonglong2 p = *(const ulonglong2*)(hh + q * 4);  // LDS.128
            ffma2(acc[(q & 3) * 2],     wp[2 * q],     p.x);
            ffma2(acc[(q & 3) * 2 + 1], wp[2 * q + 1], p.y);
        }
        // Packed reduction tree (depth 3) + scalar fold + pair-combine shfl.
        unsigned long long t0 = fadd2(acc[0], acc[1]);
        unsigned long long t1 = fadd2(acc[2], acc[3]);
        unsigned long long t2 = fadd2(acc[4], acc[5]);
        unsigned long long t3 = fadd2(acc[6], acc[7]);
        unsigned long long u  = fadd2(fadd2(t0, t1), fadd2(t2, t3));
        float2 f = unpack2(u);
        float   part = f.x + f.y;
        part += __shfl_xor_sync(0xFFFFFFFFu, part, 1);   // combine k-halves

        hn = fast_tanh(xc + part);

        if (half == 0) hbuf[cur ^ 1][j] = hn;   // one writer per unit
        xc = xn; xn = xf;
        cur ^= 1;
        __syncthreads();
    }

    if (half == 0) out[row * DH + j] = hn;
}

// ---------------------------------------------------------------------------
// Launch.
// ---------------------------------------------------------------------------
extern "C" void kernel_launch(void* const* d_in, const int* in_sizes, int n_in,
                              void* d_out, int out_size) {
    const float* input = nullptr;
    const float* Wih   = nullptr;
    const float* Whh   = nullptr;
    const float* bA    = nullptr;
    const float* bB    = nullptr;

    for (int i = 0; i < n_in; i++) {
        const int sz = in_sizes[i];
        const float* p = (const float*)d_in[i];
        if      (sz == SEQ * BATCH * DIN) input = p;
        else if (sz == DH * DIN)          Wih   = p;
        else if (sz == DH * DH)           Whh   = p;
        else if (sz == DH)                { if (!bA) bA = p; else bB = p; }
    }

    xproj_kernel<<<2048, 128>>>(input, Wih, bA, bB);
    rnn_scan_kernel<<<BATCH, 256>>>(Whh, (float*)d_out);
}

// round 8
// speedup vs baseline: 1.1632x; 1.1632x over previous
#include <cuda_runtime.h>
#include <cuda_bf16.h>

#define SEQ   4096
#define BATCH 256
#define DIN   64
#define DH    128

// Scratch for precomputed input projections x_proj[s][b][j].
__device__ float g_xproj[SEQ * BATCH * DH];

// ---------------------------------------------------------------------------
// Packed fp32x2 helpers (Blackwell: 2 FMAs per instruction).
// ---------------------------------------------------------------------------
__device__ __forceinline__ unsigned long long pack2(float lo, float hi) {
    unsigned long long r;
    asm("mov.b64 %0, {%1, %2};" : "=l"(r) : "f"(lo), "f"(hi));
    return r;
}

__device__ __forceinline__ float2 unpack2(unsigned long long v) {
    float2 f;
    asm("mov.b64 {%0, %1}, %2;" : "=f"(f.x), "=f"(f.y) : "l"(v));
    return f;
}

__device__ __forceinline__ void ffma2(unsigned long long& d,
                                      unsigned long long a,
                                      unsigned long long b) {
    asm("fma.rn.f32x2 %0, %1, %2, %0;" : "+l"(d) : "l"(a), "l"(b));
}

__device__ __forceinline__ unsigned long long fadd2(unsigned long long a,
                                                    unsigned long long b) {
    unsigned long long d;
    asm("add.rn.f32x2 %0, %1, %2;" : "=l"(d) : "l"(a), "l"(b));
    return d;
}

// tanh via 2x MUFU (EX2 + RCP), rel err ~2^-20.
__device__ __forceinline__ float fast_tanh(float x) {
    float e = __expf(x + x);
    return 1.0f - __fdividef(2.0f, e + 1.0f);
}

// ---------------------------------------------------------------------------
// Phase 1: x_proj[s,b,j] = dot(input[s,b,:], W_ih[j,:]) + b_ih[j] + b_hh[j]
// ---------------------------------------------------------------------------
__global__ void __launch_bounds__(128) xproj_kernel(
    const float* __restrict__ in,     // [SEQ*BATCH, DIN]
    const float* __restrict__ Wih,    // [DH, DIN]
    const float* __restrict__ bA,
    const float* __restrict__ bB)
{
    __shared__ __align__(16) float sin_t[16][DIN];   // 4 KB tile

    const int j = threadIdx.x;

    unsigned long long wp[32];
#pragma unroll
    for (int q = 0; q < 16; q++) {
        float4 v = *(const float4*)(Wih + j * DIN + q * 4);
        wp[2 * q]     = pack2(v.x, v.y);
        wp[2 * q + 1] = pack2(v.z, v.w);
    }
    const float bias = bA[j] + bB[j];

    const int ntiles = (SEQ * BATCH) / 16;
    for (int tile = blockIdx.x; tile < ntiles; tile += gridDim.x) {
        __syncthreads();   // WAR on sin_t reuse
        const float4* src = (const float4*)(in + tile * (16 * DIN));
        ((float4*)&sin_t[0][0])[j]       = src[j];
        ((float4*)&sin_t[0][0])[128 + j] = src[128 + j];
        __syncthreads();

        for (int r = 0; r < 16; r++) {
            unsigned long long acc[4] = {0ULL, 0ULL, 0ULL, 0ULL};
#pragma unroll
            for (int q = 0; q < 16; q++) {
                ulonglong2 hv = *(const ulonglong2*)&sin_t[r][q * 4];
                ffma2(acc[(q & 1) * 2],     wp[2 * q],     hv.x);
                ffma2(acc[(q & 1) * 2 + 1], wp[2 * q + 1], hv.y);
            }
            unsigned long long t = fadd2(fadd2(acc[0], acc[1]),
                                         fadd2(acc[2], acc[3]));
            float2 f = unpack2(t);
            __stcs(&g_xproj[(tile * 16 + r) * DH + j], f.x + f.y + bias);
        }
    }
}

// ---------------------------------------------------------------------------
// Phase 2: sequential scan. 256 blocks x 256 threads, one batch row per block.
//
// Quarter-split layout: thread (jp = tid>>2, q' = tid&3) owns TWO output
// units {jp, jp+64} and ONE 32-element k-slice [32q', 32q'+32). Each h-load
// feeds two dot products -> LDS:FFMA2 ratio 1:4 (halved LDS wavefronts vs
// the half-split). The 4 k-chunks are stored skewed in smem (chunk*36
// floats, 16B pad) so quarter lanes hit banks {4q, 4q+4, 4q+8, 4q+12}:
// conflict-free. Partials combine with 4 shfl.xor; lanes q'=0/1 finalize
// j / j+64. ~105 regs/thread -> 2 CTAs/SM (16 warps, 4 pipelines/SMSP).
// ---------------------------------------------------------------------------
#define CHUNK_STRIDE 36                       // 32 floats + 16B skew pad

__global__ void __launch_bounds__(256, 2) rnn_scan_kernel(
    const float* __restrict__ Whh,    // [DH, DH]
    float* __restrict__ out)          // [BATCH, DH]
{
    const int tid = threadIdx.x;
    const int jp  = tid >> 2;         // 0..63 : owns units jp and jp+64
    const int qt  = tid & 3;          // k-chunk [32*qt, 32*qt+32)
    const int row = blockIdx.x;

    // [buf][4 chunks * 36 floats] ; position of h[k] = (k>>5)*36 + (k&31)
    __shared__ __align__(16) float hbuf[2][4 * CHUNK_STRIDE];

    // W slices: rows jp and jp+64, columns [32qt, 32qt+32). 16 u64 each.
    unsigned long long wA[16], wB[16];
    {
        const float* ra = Whh + jp * DH + qt * 32;
        const float* rb = Whh + (jp + 64) * DH + qt * 32;
#pragma unroll
        for (int q = 0; q < 8; q++) {
            float4 va = *(const float4*)(ra + q * 4);
            float4 vb = *(const float4*)(rb + q * 4);
            wA[2 * q]     = pack2(va.x, va.y);
            wA[2 * q + 1] = pack2(va.z, va.w);
            wB[2 * q]     = pack2(vb.x, vb.y);
            wB[2 * q + 1] = pack2(vb.z, vb.w);
        }
    }

    // h0 = 0 (zero both buffers incl. pads; 288 floats, 256 threads).
    hbuf[0][tid % (4 * CHUNK_STRIDE)] = 0.0f;
    hbuf[1][tid % (4 * CHUNK_STRIDE)] = 0.0f;
    if (tid < 2 * 4 * CHUNK_STRIDE - 256)
        hbuf[1][112 + tid] = 0.0f;

    // x column this lane finalizes: q'=0 -> jp, q'=1 -> jp+64; others unused.
    const int xcol   = jp + 64 * (qt & 1);
    const bool fin   = (qt < 2);
    // Distance-2 x prefetch (streaming loads; x_proj is single-use).
    float xc = fin ? __ldcs(&g_xproj[(0 * BATCH + row) * DH + xcol]) : 0.0f;
    float xn = fin ? __ldcs(&g_xproj[(1 * BATCH + row) * DH + xcol]) : 0.0f;

    __syncthreads();

    int   cur = 0;
    float hn  = 0.0f;
    for (int s = 0; s < SEQ; s++) {
        const int sp = (s + 2 < SEQ) ? (s + 2) : (SEQ - 1);
        float xf = fin ? __ldcs(&g_xproj[(sp * BATCH + row) * DH + xcol]) : 0.0f;

        const float* hh = hbuf[cur] + qt * CHUNK_STRIDE;   // this lane's chunk
        unsigned long long accA[4] = {0ULL, 0ULL, 0ULL, 0ULL};
        unsigned long long accB[4] = {0ULL, 0ULL, 0ULL, 0ULL};
#pragma unroll
        for (int q = 0; q < 8; q++) {          // 8 x LDS.128, each feeds 4 FFMA2
            ulonglong2 p = *(const ulonglong2*)(hh + q * 4);
            ffma2(accA[(2 * q)     & 3], wA[2 * q],     p.x);
            ffma2(accA[(2 * q + 1) & 3], wA[2 * q + 1], p.y);
            ffma2(accB[(2 * q)     & 3], wB[2 * q],     p.x);
            ffma2(accB[(2 * q + 1) & 3], wB[2 * q + 1], p.y);
        }
        // Fold 4 chains -> scalar partials for units jp and jp+64.
        unsigned long long ta = fadd2(fadd2(accA[0], accA[1]),
                                      fadd2(accA[2], accA[3]));
        unsigned long long tb = fadd2(fadd2(accB[0], accB[1]),
                                      fadd2(accB[2], accB[3]));
        float2 fa = unpack2(ta), fb = unpack2(tb);
        float sA = fa.x + fa.y;
        float sB = fb.x + fb.y;
        // Combine the 4 k-chunks (lanes 4jp..4jp+3) via butterfly.
        sA += __shfl_xor_sync(0xFFFFFFFFu, sA, 1);
        sA += __shfl_xor_sync(0xFFFFFFFFu, sA, 2);
        sB += __shfl_xor_sync(0xFFFFFFFFu, sB, 1);
        sB += __shfl_xor_sync(0xFFFFFFFFu, sB, 2);

        if (fin) {
            const int j = xcol;                         // jp or jp+64
            hn = fast_tanh(xc + ((qt == 0) ? sA : sB));
            hbuf[cur ^ 1][(j >> 5) * CHUNK_STRIDE + (j & 31)] = hn;
        }
        xc = xn; xn = xf;
        cur ^= 1;
        __syncthreads();
    }

    if (fin) out[row * DH + xcol] = hn;
}

// ---------------------------------------------------------------------------
// Launch.
// ---------------------------------------------------------------------------
extern "C" void kernel_launch(void* const* d_in, const int* in_sizes, int n_in,
                              void* d_out, int out_size) {
    const float* input = nullptr;
    const float* Wih   = nullptr;
    const float* Whh   = nullptr;
    const float* bA    = nullptr;
    const float* bB    = nullptr;

    for (int i = 0; i < n_in; i++) {
        const int sz = in_sizes[i];
        const float* p = (const float*)d_in[i];
        if      (sz == SEQ * BATCH * DIN) input = p;
        else if (sz == DH * DIN)          Wih   = p;
        else if (sz == DH * DH)           Whh   = p;
        else if (sz == DH)                { if (!bA) bA = p; else bB = p; }
    }

    xproj_kernel<<<2048, 128>>>(input, Wih, bA, bB);
    rnn_scan_kernel<<<BATCH, 256>>>(Whh, (float*)d_out);
}

// round 9
// speedup vs baseline: 1.3795x; 1.1859x over previous
#include <cuda_runtime.h>
#include <cuda_bf16.h>

#define SEQ   4096
#define BATCH 256
#define DIN   64
#define DH    128

// Scratch for precomputed input projections x_proj[s][b][j].
__device__ float g_xproj[SEQ * BATCH * DH];

// ---------------------------------------------------------------------------
// Packed fp32x2 helpers (Blackwell: 2 FMAs per instruction, rt=2/SMSP).
// ---------------------------------------------------------------------------
__device__ __forceinline__ unsigned long long pack2(float lo, float hi) {
    unsigned long long r;
    asm("mov.b64 %0, {%1, %2};" : "=l"(r) : "f"(lo), "f"(hi));
    return r;
}

__device__ __forceinline__ float2 unpack2(unsigned long long v) {
    float2 f;
    asm("mov.b64 {%0, %1}, %2;" : "=f"(f.x), "=f"(f.y) : "l"(v));
    return f;
}

__device__ __forceinline__ void ffma2(unsigned long long& d,
                                      unsigned long long a,
                                      unsigned long long b) {
    asm("fma.rn.f32x2 %0, %1, %2, %0;" : "+l"(d) : "l"(a), "l"(b));
}

__device__ __forceinline__ unsigned long long fadd2(unsigned long long a,
                                                    unsigned long long b) {
    unsigned long long d;
    asm("add.rn.f32x2 %0, %1, %2;" : "=l"(d) : "l"(a), "l"(b));
    return d;
}

// tanh via 2x MUFU (EX2 + RCP), rel err ~2^-20 (tanh.approx's 6e-4 would
// accumulate past the 1e-3 gate; this keeps final rel_err ~3e-7).
__device__ __forceinline__ float fast_tanh(float x) {
    float e = __expf(x + x);
    return 1.0f - __fdividef(2.0f, e + 1.0f);
}

// ---------------------------------------------------------------------------
// Phase 1: x_proj[s,b,j] = dot(input[s,b,:], W_ih[j,:]) + b_ih[j] + b_hh[j]
// ---------------------------------------------------------------------------
__global__ void __launch_bounds__(128) xproj_kernel(
    const float* __restrict__ in,     // [SEQ*BATCH, DIN]
    const float* __restrict__ Wih,    // [DH, DIN]
    const float* __restrict__ bA,
    const float* __restrict__ bB)
{
    __shared__ __align__(16) float sin_t[16][DIN];   // 4 KB tile

    const int j = threadIdx.x;

    unsigned long long wp[32];
#pragma unroll
    for (int q = 0; q < 16; q++) {
        float4 v = *(const float4*)(Wih + j * DIN + q * 4);
        wp[2 * q]     = pack2(v.x, v.y);
        wp[2 * q + 1] = pack2(v.z, v.w);
    }
    const float bias = bA[j] + bB[j];

    const int ntiles = (SEQ * BATCH) / 16;
    for (int tile = blockIdx.x; tile < ntiles; tile += gridDim.x) {
        __syncthreads();   // WAR on sin_t reuse
        const float4* src = (const float4*)(in + tile * (16 * DIN));
        ((float4*)&sin_t[0][0])[j]       = src[j];
        ((float4*)&sin_t[0][0])[128 + j] = src[128 + j];
        __syncthreads();

        for (int r = 0; r < 16; r++) {
            unsigned long long acc[4] = {0ULL, 0ULL, 0ULL, 0ULL};
#pragma unroll
            for (int q = 0; q < 16; q++) {
                ulonglong2 hv = *(const ulonglong2*)&sin_t[r][q * 4];
                ffma2(acc[(q & 1) * 2],     wp[2 * q],     hv.x);
                ffma2(acc[(q & 1) * 2 + 1], wp[2 * q + 1], hv.y);
            }
            unsigned long long t = fadd2(fadd2(acc[0], acc[1]),
                                         fadd2(acc[2], acc[3]));
            float2 f = unpack2(t);
            __stcs(&g_xproj[(tile * 16 + r) * DH + j], f.x + f.y + bias);
        }
    }
}

// ---------------------------------------------------------------------------
// Phase 2: sequential scan. 256 blocks x 128 threads, one batch row per block.
//
// Thread j owns output unit j with the FULL k=128 dot product:
//   - W_hh row j register-resident (64 packed f32x2 = 128 regs)
//   - h read from smem as pure broadcast (all lanes same address ->
//     1 wavefront per LDS.128, zero bank conflicts by construction)
//   - NO shuffles, NO cross-lane reduction: tail = fadd2 tree + tanh + STS
//   - 4-warp barrier groups (vs 8 before): cheaper BAR, less lockstep burst
//   - 2 independent CTAs/SM (~170 regs/thread) desynchronize pipe usage
// Loop unrolled x2 with explicit buffer alternation (no cur^=1 ALU).
// ---------------------------------------------------------------------------
__device__ __forceinline__ float scan_step(
    const float* __restrict__ h,                 // smem, current h (128)
    const unsigned long long* __restrict__ wp,   // 64 packed W pairs
    float x)
{
    unsigned long long acc[8] = {0ULL,0ULL,0ULL,0ULL,0ULL,0ULL,0ULL,0ULL};
#pragma unroll
    for (int q = 0; q < 32; q++) {               // 32x LDS.128 broadcast
        ulonglong2 p = *(const ulonglong2*)(h + q * 4);
        ffma2(acc[(2 * q)     & 7], wp[2 * q],     p.x);
        ffma2(acc[(2 * q + 1) & 7], wp[2 * q + 1], p.y);
    }
    unsigned long long t0 = fadd2(acc[0], acc[1]);
    unsigned long long t1 = fadd2(acc[2], acc[3]);
    unsigned long long t2 = fadd2(acc[4], acc[5]);
    unsigned long long t3 = fadd2(acc[6], acc[7]);
    unsigned long long u  = fadd2(fadd2(t0, t1), fadd2(t2, t3));
    float2 f = unpack2(u);
    return fast_tanh(x + (f.x + f.y));
}

__global__ void __launch_bounds__(128, 2) rnn_scan_kernel(
    const float* __restrict__ Whh,    // [DH, DH]
    float* __restrict__ out)          // [BATCH, DH]
{
    const int j   = threadIdx.x;      // output unit 0..127
    const int row = blockIdx.x;

    __shared__ __align__(16) float h0buf[DH];
    __shared__ __align__(16) float h1buf[DH];

    // Full W_hh row j: 64 packed f32x2 pairs (128 registers).
    unsigned long long wp[64];
#pragma unroll
    for (int q = 0; q < 32; q++) {
        float4 v = *(const float4*)(Whh + j * DH + q * 4);
        wp[2 * q]     = pack2(v.x, v.y);
        wp[2 * q + 1] = pack2(v.z, v.w);
    }

    h0buf[j] = 0.0f;                  // h0 = 0

    const float* xcol = &g_xproj[row * DH + j];
    // Distance-2 prefetch (streaming: x_proj is single-use).
    float xc = __ldcs(xcol + 0 * BATCH * DH);
    float xn = __ldcs(xcol + 1 * BATCH * DH);

    __syncthreads();

    float hn = 0.0f;
    for (int s = 0; s < SEQ; s += 2) {
        // --- even step: read h0buf, write h1buf ---
        float xf0 = __ldcs(xcol + (size_t)min(s + 2, SEQ - 1) * (BATCH * DH));
        hn = scan_step(h0buf, wp, xc);
        h1buf[j] = hn;
        xc = xn; xn = xf0;
        __syncthreads();

        // --- odd step: read h1buf, write h0buf ---
        float xf1 = __ldcs(xcol + (size_t)min(s + 3, SEQ - 1) * (BATCH * DH));
        hn = scan_step(h1buf, wp, xc);
        h0buf[j] = hn;
        xc = xn; xn = xf1;
        __syncthreads();
    }

    out[row * DH + j] = hn;
}

// ---------------------------------------------------------------------------
// Launch.
// ---------------------------------------------------------------------------
extern "C" void kernel_launch(void* const* d_in, const int* in_sizes, int n_in,
                              void* d_out, int out_size) {
    const float* input = nullptr;
    const float* Wih   = nullptr;
    const float* Whh   = nullptr;
    const float* bA    = nullptr;
    const float* bB    = nullptr;

    for (int i = 0; i < n_in; i++) {
        const int sz = in_sizes[i];
        const float* p = (const float*)d_in[i];
        if      (sz == SEQ * BATCH * DIN) input = p;
        else if (sz == DH * DIN)          Wih   = p;
        else if (sz == DH * DH)           Whh   = p;
        else if (sz == DH)                { if (!bA) bA = p; else bB = p; }
    }

    xproj_kernel<<<2048, 128>>>(input, Wih, bA, bB);
    rnn_scan_kernel<<<BATCH, 128>>>(Whh, (float*)d_out);
}